// round 16
// baseline (speedup 1.0000x reference)
#include <cuda_runtime.h>
#include <cuda_fp16.h>
#include <cstdint>

#define BB 4
#define CC 64
#define HH 48
#define WW 64
#define NN (HH*WW)        // 3072
#define BM 128
#define BN 128
#define NTILE (NN/BM)     // 24
#define KC 32             // K chunk (halves)
#define LDK 40            // smem row stride in halves (80B): ldmatrix conflict-free
#define TILEB (BM*LDK*2)  // one tile array in bytes (10240)
#define DSMEM_BYTES (2*3*TILEB)   // double-buffered 3 arrays = 61440
#define NINF_BITS 0xFF800000u

// ---------------- device scratch ----------------
__device__ float g_srcT[BB*NN*CC];
__device__ float g_tgtT[BB*NN*CC];
__device__ float g_sd[BB*NN*CC];     // f32 descriptors (finalize)
__device__ float g_td[BB*NN*CC];
__device__ __half g_sdh[BB*NN*CC];   // A: fp16 hi only
__device__ __half g_tdh[BB*NN*CC];   // B: fp16 hi
__device__ __half g_tdl[BB*NN*CC];   // B: fp16 lo
__device__ unsigned long long g_row_all[BB*NN];
__device__ unsigned long long g_row_un [BB*NN];
__device__ unsigned long long g_col_all[BB*NN];
__device__ unsigned long long g_col_un [BB*NN];
__device__ float g_acc[2];
__device__ unsigned g_done;

// ---------------- key packing (u64 global) ----------------
__device__ __forceinline__ unsigned long long make_key(float f, int idx) {
    unsigned u = __float_as_uint(f);
    u = (u & 0x80000000u) ? ~u : (u | 0x80000000u);
    return ((unsigned long long)u << 32) | (unsigned)(0xFFFFFFFFu - (unsigned)idx);
}
__device__ __forceinline__ float key_dot(unsigned long long k) {
    unsigned u = (unsigned)(k >> 32);
    return (u & 0x80000000u) ? __uint_as_float(u ^ 0x80000000u) : __uint_as_float(~u);
}
__device__ __forceinline__ int key_idx(unsigned long long k) {
    return (int)(0xFFFFFFFFu - (unsigned)(k & 0xFFFFFFFFu));
}
__device__ __forceinline__ float dist_from_dot(float d) {
    d = fminf(fmaxf(d, -1.f), 1.f);
    return sqrtf(fmaxf(2.f - 2.f*d, 0.f));
}
__device__ __forceinline__ float decode_valf(float k) {
    return __uint_as_float(__float_as_uint(k) & ~127u);
}

__device__ __forceinline__ void ldmatrix_x4(unsigned& r0, unsigned& r1, unsigned& r2,
                                            unsigned& r3, unsigned addr) {
    asm volatile("ldmatrix.sync.aligned.m8n8.x4.shared.b16 {%0,%1,%2,%3}, [%4];"
        : "=r"(r0), "=r"(r1), "=r"(r2), "=r"(r3) : "r"(addr));
}
__device__ __forceinline__ void mma_f16(float* c, unsigned a0, unsigned a1,
                                        unsigned a2, unsigned a3,
                                        unsigned b0, unsigned b1) {
    asm volatile(
        "mma.sync.aligned.m16n8k16.row.col.f32.f16.f16.f32 "
        "{%0,%1,%2,%3}, {%4,%5,%6,%7}, {%8,%9}, {%0,%1,%2,%3};\n"
        : "+f"(c[0]), "+f"(c[1]), "+f"(c[2]), "+f"(c[3])
        : "r"(a0), "r"(a1), "r"(a2), "r"(a3), "r"(b0), "r"(b1));
}
__device__ __forceinline__ void cp_async16(unsigned dst, const void* src) {
    asm volatile("cp.async.cg.shared.global [%0], [%1], 16;" :: "r"(dst), "l"(src));
}

// ---------------- 1. coalesced transpose + init ----------------
__global__ void transpose_kernel(const float* __restrict__ src, const float* __restrict__ tgt) {
    __shared__ float tile[32][33];
    int arr = blockIdx.z >> 2, b = blockIdx.z & 3;
    const float* in = arr ? tgt : src;
    float* out = arr ? g_tgtT : g_srcT;
    int p0 = blockIdx.x*32, c0 = blockIdx.y*32;
    int tx = threadIdx.x & 31, ty = threadIdx.x >> 5;
    #pragma unroll
    for (int q = 0; q < 4; q++)
        tile[ty + q*8][tx] = in[((size_t)b*CC + c0 + ty + q*8)*NN + p0 + tx];
    __syncthreads();
    #pragma unroll
    for (int q = 0; q < 4; q++)
        out[((size_t)b*NN + p0 + ty + q*8)*CC + c0 + tx] = tile[tx][ty + q*8];
    int gi = ((blockIdx.z*gridDim.y + blockIdx.y)*gridDim.x + blockIdx.x)*256 + threadIdx.x;
    if (gi < BB*NN) {
        g_row_all[gi] = 0ULL; g_row_un[gi] = 0ULL;
        g_col_all[gi] = 0ULL; g_col_un[gi] = 0ULL;
    }
    if (gi < 2) g_acc[gi] = 0.f;
    if (gi == 0) g_done = 0u;
}

// ---------------- 2. bilinear sample + normalize + fp16 (lo only for target) ----------------
__global__ void sample_kernel(const float* __restrict__ spn, const float* __restrict__ tpn) {
    int gw   = (blockIdx.x*blockDim.x + threadIdx.x) >> 5;
    int lane = threadIdx.x & 31;
    int b    = gw / (2*NN);
    int rem  = gw - b*2*NN;
    int side = rem / NN;
    int p    = rem - side*NN;

    const float* g = (side ? tpn : spn) + ((size_t)b*NN + p)*2;
    float gx = g[0], gy = g[1];
    const float* img = (side ? g_tgtT : g_srcT) + (size_t)b*NN*CC;

    float x = ((gx + 1.f)*WW - 1.f)*0.5f;
    float y = ((gy + 1.f)*HH - 1.f)*0.5f;
    float x0f = floorf(x), y0f = floorf(y);
    int x0 = (int)x0f, y0 = (int)y0f;
    int x1 = x0 + 1,   y1 = y0 + 1;
    float wx1 = x - x0f, wx0 = 1.f - wx1;
    float wy1 = y - y0f, wy0 = 1.f - wy1;

    float v0 = 0.f, v1 = 0.f;
    #define CORNER(XI, YI, WGT) do { \
        if ((XI) >= 0 && (XI) < WW && (YI) >= 0 && (YI) < HH) { \
            const float* q = img + ((size_t)(YI)*WW + (XI))*CC; \
            v0 += (WGT)*q[lane]; v1 += (WGT)*q[lane+32]; \
        } } while(0)
    CORNER(x0, y0, wx0*wy0);
    CORNER(x1, y0, wx1*wy0);
    CORNER(x0, y1, wx0*wy1);
    CORNER(x1, y1, wx1*wy1);
    #undef CORNER

    float ss = v0*v0 + v1*v1;
    #pragma unroll
    for (int m = 16; m; m >>= 1) ss += __shfl_xor_sync(0xFFFFFFFFu, ss, m);
    float inv = 1.f / fmaxf(sqrtf(ss), 1e-12f);

    size_t base = ((size_t)b*NN + p)*CC;
    float*  outf = (side ? g_td  : g_sd ) + base;
    __half* outh = (side ? g_tdh : g_sdh) + base;
    float s0 = v0*inv, s1 = v1*inv;
    outf[lane]    = s0;
    outf[lane+32] = s1;
    __half h0 = __float2half_rn(s0);
    __half h1 = __float2half_rn(s1);
    outh[lane]    = h0;
    outh[lane+32] = h1;
    if (side) {
        __half* outl = g_tdl + base;
        outl[lane]    = __float2half_rn(s0 - __half2float(h0));
        outl[lane+32] = __float2half_rn(s1 - __half2float(h1));
    }
}

// ---------------- dummy: keeps gemm at profiled launch index 3 ----------------
__global__ void dummy_kernel() {}

// ---------------- 3. fp16x2 GEMM: cp.async + ldmatrix + shared-pack argmax ----------------
__global__ void __launch_bounds__(256, 2) gemm_reduce_kernel(const float* __restrict__ tpu,
                                                             const int* __restrict__ rf) {
    extern __shared__ __align__(16) unsigned char dynsm[];
    __shared__ float pxr[BM], pyr[BM], pxc[BN], pyc[BN];

    const int b       = blockIdx.z;
    const int rowBase = blockIdx.y * BM;
    const int colBase = blockIdx.x * BN;
    const int tid     = threadIdx.x;
    const int wid     = tid >> 5;
    const int lane    = tid & 31;
    const int gid     = lane >> 2;
    const int tig     = lane & 3;

    int rv = rf[0];
    float relax = (rv >= 0 && rv < 1000000) ? (float)rv : __int_as_float(rv);

    const int rowW = (wid & 1) * 64;
    const int colW = (wid >> 1) * 32;

    const size_t baseA = ((size_t)b*NN + rowBase)*CC;
    const size_t baseB = ((size_t)b*NN + colBase)*CC;

    const unsigned dynbase = (unsigned)__cvta_generic_to_shared(dynsm);
    const float NINF = __uint_as_float(NINF_BITS);

    // ---- issue both K-chunk loads via cp.async (3 arrays: Ah, Bh, Bl) ----
    #pragma unroll
    for (int c = 0; c < 2; c++) {
        #pragma unroll
        for (int it = 0; it < 6; it++) {
            const int arr = it >> 1;
            const int idx = tid + (it & 1)*256;     // 0..511
            const int row = idx >> 2, seg = idx & 3;
            const __half* gsrc = (arr == 0) ? (g_sdh + baseA) :
                                 (arr == 1) ? (g_tdh + baseB) : (g_tdl + baseB);
            unsigned dst = dynbase + (unsigned)((c*3 + arr)*TILEB + (row*LDK + seg*8)*2);
            cp_async16(dst, gsrc + (size_t)row*CC + c*KC + seg*8);
        }
        asm volatile("cp.async.commit_group;");
    }

    if (tid < 128) {
        const float* px = tpu + (size_t)b*2*NN;
        const float* py = px + NN;
        pxr[tid] = px[rowBase + tid]; pyr[tid] = py[rowBase + tid];
        pxc[tid] = px[colBase + tid]; pyc[tid] = py[colBase + tid];
    }

    float acc[4][4][4];
    #pragma unroll
    for (int mt = 0; mt < 4; mt++)
        #pragma unroll
        for (int nt = 0; nt < 4; nt++)
            #pragma unroll
            for (int e = 0; e < 4; e++) acc[mt][nt][e] = 0.f;

    // per-lane fragment offsets (bytes)
    const unsigned aoff  = ((lane & 15)*LDK + (lane >> 4)*8) * 2;
    const unsigned bfoff = ((((lane >> 4) << 3) + (lane & 7))*LDK + ((lane >> 3) & 1)*8) * 2;

    #pragma unroll
    for (int c = 0; c < 2; c++) {
        if (c == 0) { asm volatile("cp.async.wait_group 1;"); }
        else        { asm volatile("cp.async.wait_group 0;"); }
        __syncthreads();

        const unsigned Ah_b = dynbase + (c*3 + 0)*TILEB;
        const unsigned Bh_b = dynbase + (c*3 + 1)*TILEB;
        const unsigned Bl_b = dynbase + (c*3 + 2)*TILEB;

        #pragma unroll
        for (int ks = 0; ks < 2; ks++) {
            const int kk = ks*16;
            unsigned bh[4][2], bl[4][2];
            #pragma unroll
            for (int p = 0; p < 2; p++) {
                const unsigned rel = (unsigned)(((colW + p*16)*LDK + kk)*2) + bfoff;
                ldmatrix_x4(bh[2*p][0], bh[2*p][1], bh[2*p+1][0], bh[2*p+1][1], Bh_b + rel);
                ldmatrix_x4(bl[2*p][0], bl[2*p][1], bl[2*p+1][0], bl[2*p+1][1], Bl_b + rel);
            }
            #pragma unroll
            for (int mt = 0; mt < 4; mt++) {
                const unsigned tileoff = (unsigned)(((rowW + mt*16)*LDK + kk)*2) + aoff;
                unsigned ah0, ah1, ah2, ah3;
                ldmatrix_x4(ah0, ah1, ah2, ah3, Ah_b + tileoff);
                #pragma unroll
                for (int nt = 0; nt < 4; nt++)
                    mma_f16(acc[mt][nt], ah0, ah1, ah2, ah3, bh[nt][0], bh[nt][1]);
                #pragma unroll
                for (int nt = 0; nt < 4; nt++)
                    mma_f16(acc[mt][nt], ah0, ah1, ah2, ah3, bl[nt][0], bl[nt][1]);
            }
        }
    }

    // ---- in-place shared pack: low 6 bits = code (rr<<3 | cc) ----
    // rr = mt*2+half  (row-unit id),  cc = nt*2+e  (col-unit id)
    #pragma unroll
    for (int mt = 0; mt < 4; mt++)
        #pragma unroll
        for (int nt = 0; nt < 4; nt++)
            #pragma unroll
            for (int e2 = 0; e2 < 4; e2++) {
                const unsigned code = (unsigned)(((mt*2 + (e2>>1)) << 3) | (nt*2 + (e2&1)));
                acc[mt][nt][e2] = __uint_as_float(
                    (__float_as_uint(acc[mt][nt][e2]) & ~63u) | code);
            }

    const size_t rowG = (size_t)b*NN + rowBase;
    const size_t colG = (size_t)b*NN + colBase;

    // ---- row (st) scan: fmax trees over pre-packed accs + lazy repair ----
    #pragma unroll
    for (int mt = 0; mt < 4; mt++) {
        #pragma unroll
        for (int half = 0; half < 2; half++) {
            const int r_loc = rowW + mt*16 + half*8 + gid;
            float t = acc[mt][0][half*2];
            #pragma unroll
            for (int j = 1; j < 8; j++)
                t = fmaxf(t, acc[mt][j>>1][half*2 + (j&1)]);
            {
                unsigned bits = __float_as_uint(t);
                unsigned cc = bits & 7u;
                unsigned c = (unsigned)(colW + tig*2) + ((cc>>1)<<3) + (cc&1);
                t = __uint_as_float((bits & ~127u) | (127u - c));
            }
            t = fmaxf(t, __shfl_xor_sync(0xFFFFFFFFu, t, 1));
            t = fmaxf(t, __shfl_xor_sync(0xFFFFFFFFu, t, 2));
            float k_all = t, k_un = t;
            unsigned cw = 127u - (__float_as_uint(t) & 127u);
            bool masked = (fabsf(pxc[cw]-pxr[r_loc]) <= relax) &&
                          (fabsf(pyc[cw]-pyr[r_loc]) <= relax);
            if (__any_sync(0xFFFFFFFFu, masked)) {
                unsigned exm = 0;
                bool done = !masked;
                if (masked) {
                    int d = (int)cw - colW - tig*2;
                    if (d >= 0 && d < 32 && (d & 6) == 0)
                        exm |= 1u << (((d>>3)<<1) | (d&1));
                }
                for (int it = 0; it < 40; it++) {
                    float t2 = NINF;
                    #pragma unroll
                    for (int j = 0; j < 8; j++) {
                        float kb = acc[mt][j>>1][half*2 + (j&1)];
                        if ((exm >> j) & 1u) kb = NINF;
                        t2 = fmaxf(t2, kb);
                    }
                    if (__float_as_uint(t2) != NINF_BITS) {
                        unsigned bits = __float_as_uint(t2);
                        unsigned cc = bits & 7u;
                        unsigned c2 = (unsigned)(colW + tig*2) + ((cc>>1)<<3) + (cc&1);
                        t2 = __uint_as_float((bits & ~127u) | (127u - c2));
                    }
                    t2 = fmaxf(t2, __shfl_xor_sync(0xFFFFFFFFu, t2, 1));
                    t2 = fmaxf(t2, __shfl_xor_sync(0xFFFFFFFFu, t2, 2));
                    if (!done) {
                        if (__float_as_uint(t2) == NINF_BITS) { k_un = NINF; done = true; }
                        else {
                            unsigned c2 = 127u - (__float_as_uint(t2) & 127u);
                            bool m2 = (fabsf(pxc[c2]-pxr[r_loc])<=relax) &&
                                      (fabsf(pyc[c2]-pyr[r_loc])<=relax);
                            if (!m2) { k_un = t2; done = true; }
                            else {
                                int d = (int)c2 - colW - tig*2;
                                if (d >= 0 && d < 32 && (d & 6) == 0)
                                    exm |= 1u << (((d>>3)<<1) | (d&1));
                            }
                        }
                    }
                    if (!__any_sync(0xFFFFFFFFu, !done)) break;
                }
            }
            if (tig == 0) {
                atomicMax(&g_row_all[rowG + r_loc],
                          make_key(decode_valf(k_all),
                                   colBase + (int)(127u - (__float_as_uint(k_all) & 127u))));
                if (__float_as_uint(k_un) != NINF_BITS)
                    atomicMax(&g_row_un[rowG + r_loc],
                              make_key(decode_valf(k_un),
                                       colBase + (int)(127u - (__float_as_uint(k_un) & 127u))));
            }
        }
    }

    // ---- col (ts) scan ----
    #pragma unroll
    for (int nt = 0; nt < 4; nt++) {
        #pragma unroll
        for (int e = 0; e < 2; e++) {
            const int c_loc = colW + nt*8 + tig*2 + e;
            float t = acc[0][nt][e];
            #pragma unroll
            for (int j = 1; j < 8; j++)
                t = fmaxf(t, acc[j>>1][nt][(j&1)*2 + e]);
            {
                unsigned bits = __float_as_uint(t);
                unsigned rr = (bits >> 3) & 7u;
                unsigned r = (unsigned)(rowW + gid) + ((rr>>1)<<4) + ((rr&1)<<3);
                t = __uint_as_float((bits & ~127u) | (127u - r));
            }
            t = fmaxf(t, __shfl_xor_sync(0xFFFFFFFFu, t, 4));
            t = fmaxf(t, __shfl_xor_sync(0xFFFFFFFFu, t, 8));
            t = fmaxf(t, __shfl_xor_sync(0xFFFFFFFFu, t, 16));
            float k_all = t, k_un = t;
            unsigned rw = 127u - (__float_as_uint(t) & 127u);
            bool masked = (fabsf(pxr[rw]-pxc[c_loc]) <= relax) &&
                          (fabsf(pyr[rw]-pyc[c_loc]) <= relax);
            if (__any_sync(0xFFFFFFFFu, masked)) {
                unsigned exm = 0;
                bool done = !masked;
                if (masked) {
                    int d = (int)rw - rowW - gid;
                    if (d >= 0 && d < 64 && (d & 7) == 0)
                        exm |= 1u << (((d>>4)<<1) | ((d>>3)&1));
                }
                for (int it = 0; it < 70; it++) {
                    float t2 = NINF;
                    #pragma unroll
                    for (int j = 0; j < 8; j++) {
                        float kb = acc[j>>1][nt][(j&1)*2 + e];
                        if ((exm >> j) & 1u) kb = NINF;
                        t2 = fmaxf(t2, kb);
                    }
                    if (__float_as_uint(t2) != NINF_BITS) {
                        unsigned bits = __float_as_uint(t2);
                        unsigned rr = (bits >> 3) & 7u;
                        unsigned r2 = (unsigned)(rowW + gid) + ((rr>>1)<<4) + ((rr&1)<<3);
                        t2 = __uint_as_float((bits & ~127u) | (127u - r2));
                    }
                    t2 = fmaxf(t2, __shfl_xor_sync(0xFFFFFFFFu, t2, 4));
                    t2 = fmaxf(t2, __shfl_xor_sync(0xFFFFFFFFu, t2, 8));
                    t2 = fmaxf(t2, __shfl_xor_sync(0xFFFFFFFFu, t2, 16));
                    if (!done) {
                        if (__float_as_uint(t2) == NINF_BITS) { k_un = NINF; done = true; }
                        else {
                            unsigned r2 = 127u - (__float_as_uint(t2) & 127u);
                            bool m2 = (fabsf(pxr[r2]-pxc[c_loc])<=relax) &&
                                      (fabsf(pyr[r2]-pyc[c_loc])<=relax);
                            if (!m2) { k_un = t2; done = true; }
                            else {
                                int d = (int)r2 - rowW - gid;
                                if (d >= 0 && d < 64 && (d & 7) == 0)
                                    exm |= 1u << (((d>>4)<<1) | ((d>>3)&1));
                            }
                        }
                    }
                    if (!__any_sync(0xFFFFFFFFu, !done)) break;
                }
            }
            if (gid == 0) {
                atomicMax(&g_col_all[colG + c_loc],
                          make_key(decode_valf(k_all),
                                   rowBase + (int)(127u - (__float_as_uint(k_all) & 127u))));
                if (__float_as_uint(k_un) != NINF_BITS)
                    atomicMax(&g_col_un[colG + c_loc],
                              make_key(decode_valf(k_un),
                                       rowBase + (int)(127u - (__float_as_uint(k_un) & 127u))));
            }
        }
    }
}

// ---------------- 4. triplet loss + recall + fused writeout ----------------
__global__ void finalize_kernel(const float* __restrict__ tpu, float* __restrict__ out) {
    __shared__ float s_loss[8], s_corr[8];
    int gw   = (blockIdx.x*blockDim.x + threadIdx.x) >> 5;
    int lane = threadIdx.x & 31;
    int warp = threadIdx.x >> 5;

    int b = gw / NN;
    int i = gw - b*NN;
    const float* px = tpu + (size_t)b*2*NN;
    const float* py = px + NN;
    size_t base = (size_t)b*NN + i;

    unsigned long long kra = g_row_all[base];
    unsigned long long kru = g_row_un [base];
    unsigned long long kca = g_col_all[base];
    unsigned long long kcu = g_col_un [base];

    int nn_st = key_idx(kra);
    int nn_ts = key_idx(kca);
    int neg_st, neg_ts;
    float d_st, d_ts;
    if (kru == 0ULL) { neg_st = 0; d_st = 2.f; }
    else { neg_st = key_idx(kru); d_st = dist_from_dot(key_dot(kru)); }
    if (kcu == 0ULL) { neg_ts = 0; d_ts = 2.f; }
    else { neg_ts = key_idx(kcu); d_ts = dist_from_dot(key_dot(kcu)); }

    bool take_ts = d_ts < d_st;
    const float* a = (take_ts ? g_td : g_sd) + base*CC;
    const float* p = (take_ts ? g_sd : g_td) + base*CC;
    const float* n = take_ts ? (g_sd + ((size_t)b*NN + neg_ts)*CC)
                             : (g_td + ((size_t)b*NN + neg_st)*CC);

    float dp2 = 0.f, dn2 = 0.f;
    {
        float2 av = *(const float2*)(a + 2*lane);
        float2 pv = *(const float2*)(p + 2*lane);
        float2 nv = *(const float2*)(n + 2*lane);
        float e1 = av.x - pv.x + 1e-6f; dp2 = fmaf(e1, e1, dp2);
        float e2 = av.y - pv.y + 1e-6f; dp2 = fmaf(e2, e2, dp2);
        float e3 = av.x - nv.x + 1e-6f; dn2 = fmaf(e3, e3, dn2);
        float e4 = av.y - nv.y + 1e-6f; dn2 = fmaf(e4, e4, dn2);
    }
    #pragma unroll
    for (int m = 16; m; m >>= 1) {
        dp2 += __shfl_xor_sync(0xFFFFFFFFu, dp2, m);
        dn2 += __shfl_xor_sync(0xFFFFFFFFu, dn2, m);
    }
    if (lane == 0) {
        float loss = fmaxf(sqrtf(dp2) - sqrtf(dn2) + 0.2f, 0.f);
        float corr = 0.f;
        float pxi = px[i], pyi = py[i];
        if (px[nn_st] == pxi && py[nn_st] == pyi) corr += 1.f;
        if (px[nn_ts] == pxi && py[nn_ts] == pyi) corr += 1.f;
        s_loss[warp] = loss;
        s_corr[warp] = corr;
    }
    __syncthreads();
    if (threadIdx.x == 0) {
        float L = 0.f, Cr = 0.f;
        #pragma unroll
        for (int w = 0; w < 8; w++) { L += s_loss[w]; Cr += s_corr[w]; }
        atomicAdd(&g_acc[0], L);
        atomicAdd(&g_acc[1], Cr);
        __threadfence();
        unsigned t = atomicAdd(&g_done, 1u);
        if (t == gridDim.x - 1) {
            __threadfence();
            out[0] = g_acc[0] / (float)(BB*NN);
            out[1] = g_acc[1] / (float)(2*BB*NN);
        }
    }
}

// ---------------- launch ----------------
extern "C" void kernel_launch(void* const* d_in, const int* in_sizes, int n_in,
                              void* d_out, int out_size) {
    const float* src = (const float*)d_in[0];
    const float* tgt = (const float*)d_in[1];
    const float* spn = (const float*)d_in[2];
    const float* tpn = (const float*)d_in[3];
    const float* tpu = (const float*)d_in[4];
    const int*   rf  = (const int*)  d_in[5];
    float* out = (float*)d_out;

    cudaFuncSetAttribute(gemm_reduce_kernel,
                         cudaFuncAttributeMaxDynamicSharedMemorySize, DSMEM_BYTES);

    dim3 tgrid(NN/32, CC/32, BB*2);
    transpose_kernel<<<tgrid, 256>>>(src, tgt);              // launch 0
    sample_kernel<<<(BB*2*NN)/8, 256>>>(spn, tpn);           // launch 1
    dummy_kernel<<<1, 32>>>();                               // launch 2 (profiling shim)

    dim3 grid(NTILE, NTILE, BB);
    gemm_reduce_kernel<<<grid, 256, DSMEM_BYTES>>>(tpu, rf); // launch 3 -> ncu target

    finalize_kernel<<<(BB*NN)/8, 256>>>(tpu, out);           // launch 4 (fused writeout)
}